// round 16
// baseline (speedup 1.0000x reference)
#include <cuda_runtime.h>
#include <cuda_fp16.h>
#include <cstdint>
#include <math.h>

// ---------------------------------------------------------------------------
// B=16, T=2048, M=4, D=128, F=256, H=4, C=64
// Nf = 32768 frames, Nrows = 131072
// Toolchain targets sm_100 (no 'a') -> legacy mma.sync fp16 path.
// GEMM: BM=128 BN=128, 256 thr, 3-stage cp.async, 2 CTAs/SM (R13-proven).
// attn: R13 staging (16 KB smem, 2 frames/block) + lane-owns-8-features layout
//       (no alpha broadcast, 128-bit smem accesses).
// ---------------------------------------------------------------------------
#define NFRAMES   32768
#define NROWS     131072
#define DIM_D     128
#define DIM_F     256
#define DIM_QKVS  1024

__device__ __half g_x[NROWS * DIM_D];          // 32 MB: x in fp16
__device__ __half g_h[NROWS * DIM_F];          // 64 MB: hidden activations
__device__ __half g_qkvs[NROWS * DIM_QKVS];    // 256 MB: fused q|k|v|s
__device__ __half g_wemb[DIM_F * DIM_D];       // emb weights [N][K]
__device__ __half g_w1[DIM_QKVS * DIM_F];      // conv1 packed weights [N][K]
__device__ __half g_w2[DIM_QKVS * DIM_F];      // conv2 packed weights [N][K]
__device__ float  g_bemb[DIM_F];
__device__ float  g_b1[DIM_QKVS];
__device__ float  g_b2[DIM_QKVS];

__device__ __forceinline__ uint32_t swz(uint32_t off) {   // 128B-row XOR swizzle
    return off ^ ((off >> 3) & 0x70);
}

#define CP_ASYNC16(dst, src) \
    asm volatile("cp.async.cg.shared.global [%0], [%1], 16;" :: "r"(dst), "l"(src))
#define CP_COMMIT() asm volatile("cp.async.commit_group;")
#define CP_WAIT1()  asm volatile("cp.async.wait_group 1;" ::: "memory")
#define CP_WAIT0()  asm volatile("cp.async.wait_group 0;" ::: "memory")

#define LDSM_X4(r, addr)                                                        \
    asm volatile("ldmatrix.sync.aligned.m8n8.x4.shared.b16 {%0,%1,%2,%3}, [%4];" \
                 : "=r"((r)[0]), "=r"((r)[1]), "=r"((r)[2]), "=r"((r)[3])        \
                 : "r"(addr))

#define MMA_F16(c, a, b0v, b1v)                                                 \
    asm volatile("mma.sync.aligned.m16n8k16.row.col.f32.f16.f16.f32 "           \
                 "{%0,%1,%2,%3},{%4,%5,%6,%7},{%8,%9},{%0,%1,%2,%3};"           \
                 : "+f"((c)[0]), "+f"((c)[1]), "+f"((c)[2]), "+f"((c)[3])        \
                 : "r"((a)[0]), "r"((a)[1]), "r"((a)[2]), "r"((a)[3]),           \
                   "r"(b0v), "r"(b1v))

// ---------------------------------------------------------------------------
// fp16 mma.sync GEMM (R13-proven config, unchanged).
// ---------------------------------------------------------------------------
#define ASZ (128 * 128)      // 16 KB (128 rows x 128 B)
#define BSZ (128 * 128)      // 16 KB
#define GEMM_SMEM (3 * (ASZ + BSZ))   // 98304 B -> 2 CTAs/SM

template <int NCHUNKS>
__global__ __launch_bounds__(256, 2)
void gemm_f16(const __half* __restrict__ A, const __half* __restrict__ Wt,
              const float* __restrict__ bias, __half* __restrict__ C,
              int NC, int relu)
{
    constexpr int K = NCHUNKS * 64;
    extern __shared__ __align__(128) char smem[];
    const uint32_t smem_u = (uint32_t)__cvta_generic_to_shared(smem);
    const uint32_t a_u = smem_u;
    const uint32_t b_u = smem_u + 3 * ASZ;

    const int tid  = threadIdx.x;
    const int lane = tid & 31;
    const int wid  = tid >> 5;
    const int wm   = wid >> 1;
    const int wn   = wid & 1;
    const int row0 = blockIdx.y * 128;
    const int col0 = blockIdx.x * 128;

    float acc[2][8][4];
#pragma unroll
    for (int mi = 0; mi < 2; mi++)
#pragma unroll
        for (int nf = 0; nf < 8; nf++)
#pragma unroll
            for (int c = 0; c < 4; c++) acc[mi][nf][c] = 0.f;

    const int ac = tid & 7;

    auto stage = [&](int s, int c) {
        const int k0 = c * 64;
        const uint32_t abase = a_u + s * ASZ;
        const uint32_t bbase = b_u + s * BSZ;
#pragma unroll
        for (int t = 0; t < 4; t++) {
            int rr = (tid + t * 256) >> 3;
            const __half* src = A + (size_t)(row0 + rr) * K + k0 + ac * 8;
            CP_ASYNC16(abase + swz(rr * 128 + ac * 16), src);
        }
#pragma unroll
        for (int t = 0; t < 4; t++) {
            int rr = (tid + t * 256) >> 3;
            const __half* src = Wt + (size_t)(col0 + rr) * K + k0 + ac * 8;
            CP_ASYNC16(bbase + swz(rr * 128 + ac * 16), src);
        }
    };

    stage(0, 0); CP_COMMIT();
    if (NCHUNKS > 1) stage(1, 1);
    CP_COMMIT();

    const int arow0 = wm * 32 + (lane & 15);
    const int ahc   = lane >> 4;
    const int brow0 = wn * 64 + (lane & 7) + ((lane >> 4) & 1) * 8;
    const int bhc   = (lane >> 3) & 1;

#pragma unroll
    for (int c = 0; c < NCHUNKS; c++) {
        const int s = c % 3;
        CP_WAIT1();
        __syncthreads();
        if (c + 2 < NCHUNKS) stage((c + 2) % 3, c + 2);
        CP_COMMIT();

        const uint32_t asb = a_u + s * ASZ;
        const uint32_t bsb = b_u + s * BSZ;
#pragma unroll
        for (int ks = 0; ks < 4; ks++) {
            unsigned a[2][4];
#pragma unroll
            for (int mi = 0; mi < 2; mi++) {
                int row = arow0 + mi * 16;
                int ch  = (ks * 2 + ahc) ^ (row & 7);
                LDSM_X4(a[mi], asb + (uint32_t)(row * 128 + ch * 16));
            }
            unsigned b[4][4];
#pragma unroll
            for (int p = 0; p < 4; p++) {
                int row = brow0 + p * 16;
                int ch  = (ks * 2 + bhc) ^ (row & 7);
                LDSM_X4(b[p], bsb + (uint32_t)(row * 128 + ch * 16));
            }
#pragma unroll
            for (int mi = 0; mi < 2; mi++)
#pragma unroll
                for (int nf = 0; nf < 8; nf++)
                    MMA_F16(acc[mi][nf], a[mi],
                            b[nf >> 1][(nf & 1) * 2], b[nf >> 1][(nf & 1) * 2 + 1]);
        }
        __syncthreads();
    }

    const int g = lane >> 2, t = lane & 3;
    float2 bb[8];
#pragma unroll
    for (int nf = 0; nf < 8; nf++)
        bb[nf] = *(const float2*)&bias[col0 + wn * 64 + nf * 8 + t * 2];

    CP_WAIT0();

#pragma unroll
    for (int mi = 0; mi < 2; mi++) {
        int row = row0 + wm * 32 + mi * 16 + g;
#pragma unroll
        for (int nf = 0; nf < 8; nf++) {
            int col = col0 + wn * 64 + nf * 8 + t * 2;
            float2 v0 = make_float2(acc[mi][nf][0] + bb[nf].x, acc[mi][nf][1] + bb[nf].y);
            float2 v1 = make_float2(acc[mi][nf][2] + bb[nf].x, acc[mi][nf][3] + bb[nf].y);
            if (relu) {
                v0.x = fmaxf(v0.x, 0.f); v0.y = fmaxf(v0.y, 0.f);
                v1.x = fmaxf(v1.x, 0.f); v1.y = fmaxf(v1.y, 0.f);
            }
            *(__half2*)&C[(size_t)row * NC + col]       = __floats2half2_rn(v0.x, v0.y);
            *(__half2*)&C[(size_t)(row + 8) * NC + col] = __floats2half2_rn(v1.x, v1.y);
        }
    }
}

// ---------------------------------------------------------------------------
// Merged prep: convert x to fp16 + transpose-pack all weights (one launch).
// ---------------------------------------------------------------------------
__device__ __forceinline__ void pack4_body(int idx,
    const float* qw, const float* kw, const float* vw, const float* sw,
    const float* qb, const float* kb, const float* vb, const float* sb,
    __half* wTo, float* bo)
{
    int k = idx & 255;
    int n = idx >> 8;
    int sel = n >> 8, jj = n & 255;
    const float* w = (sel == 0) ? qw : (sel == 1) ? kw : (sel == 2) ? vw : sw;
    wTo[(size_t)n * 256 + k] = __float2half(w[(size_t)k * 256 + jj]);
    if (idx < DIM_QKVS) {
        int s2 = idx >> 8, j2 = idx & 255;
        const float* b = (s2 == 0) ? qb : (s2 == 1) ? kb : (s2 == 2) ? vb : sb;
        bo[idx] = b[j2];
    }
}

__global__ void prep_all(const float* __restrict__ x, __half* __restrict__ xh,
                         const float* emb_w, const float* emb_b,
                         const float* q1w, const float* k1w, const float* v1w, const float* s1w,
                         const float* q1b, const float* k1b, const float* v1b, const float* s1b,
                         const float* q2w, const float* k2w, const float* v2w, const float* s2w,
                         const float* q2b, const float* k2b, const float* v2b, const float* s2b)
{
    const int bid = blockIdx.x;
    const int tid = threadIdx.x;
    if (bid < 16384) {
        int i = bid * 256 + tid;
        float4 v = ((const float4*)x)[i];
        ((__half2*)xh)[2 * i]     = __floats2half2_rn(v.x, v.y);
        ((__half2*)xh)[2 * i + 1] = __floats2half2_rn(v.z, v.w);
    } else if (bid < 16512) {
        int idx = (bid - 16384) * 256 + tid;
        int k = idx % DIM_D;
        int n = idx / DIM_D;
        g_wemb[(size_t)n * DIM_D + k] = __float2half(emb_w[(size_t)k * 256 + n]);
        if (idx < 256) g_bemb[idx] = emb_b[idx];
    } else if (bid < 17536) {
        pack4_body((bid - 16512) * 256 + tid, q1w, k1w, v1w, s1w,
                   q1b, k1b, v1b, s1b, g_w1, g_b1);
    } else {
        pack4_body((bid - 17536) * 256 + tid, q2w, k2w, v2w, s2w,
                   q2b, k2b, v2b, s2b, g_w2, g_b2);
    }
}

// ---------------------------------------------------------------------------
// Fused attention + beta skip + LayerNorm + ReLU.
// Block = 256 thr = 8 warps = 2 frames x 4 nodes (R13 staging).
// Lane owns features f = lane*8..+7; feature head (lane>>3) == dot head ->
// no alpha broadcast; all smem accesses 128-bit, conflict-free.
// ---------------------------------------------------------------------------
__device__ __forceinline__ float warp_sum(float v) {
#pragma unroll
    for (int o = 16; o > 0; o >>= 1) v += __shfl_xor_sync(0xffffffffu, v, o);
    return v;
}

__device__ __forceinline__ void cvt8(uint4 u, float* f) {
    const __half2* h = (const __half2*)&u;
#pragma unroll
    for (int i = 0; i < 4; i++) {
        float2 t = __half22float2(h[i]);
        f[2 * i] = t.x; f[2 * i + 1] = t.y;
    }
}

__device__ __forceinline__ void store8(__half* p, const float* v) {
    uint4 u;
    __half2* h = (__half2*)&u;
#pragma unroll
    for (int i = 0; i < 4; i++) h[i] = __floats2half2_rn(v[2 * i], v[2 * i + 1]);
    *(uint4*)p = u;
}
__device__ __forceinline__ void store8(float* p, const float* v) {
    ((float4*)p)[0] = make_float4(v[0], v[1], v[2], v[3]);
    ((float4*)p)[1] = make_float4(v[4], v[5], v[6], v[7]);
}

template <typename OutT>
__global__ __launch_bounds__(256)
void attn_ln_kernel(const __half* __restrict__ qkvs, const float* __restrict__ bw,
                    const float* __restrict__ ln_g, const float* __restrict__ ln_b,
                    OutT* __restrict__ out)
{
    __shared__ __align__(16) __half s_all[8192];   // 2 frames x 4 nodes x 1024

    const int tid  = threadIdx.x;
    const int lane = tid & 31;
    const int wid  = tid >> 5;
    const int fl   = wid >> 2;      // frame within block (0/1)
    const int node = wid & 3;

    // stage 2 contiguous frames (16 KB = 1024 uint4): 4 per thread
    {
        const uint4* src = (const uint4*)(qkvs + (size_t)blockIdx.x * 8192);
        uint4* dst = (uint4*)s_all;
#pragma unroll
        for (int r = 0; r < 4; r++) dst[tid + r * 256] = src[tid + r * 256];
    }
    __syncthreads();

    const __half* fr = s_all + fl * 4096;
    const int h = lane >> 3, sub = lane & 7;

    // dots: each lane handles 8 channels of head h; xor-reduce within 8 lanes
    float dot[4];
    {
        float q8[8];
        cvt8(*(const uint4*)(fr + node * 1024 + h * 64 + sub * 8), q8);
#pragma unroll
        for (int j = 0; j < 4; j++) {
            float k8[8];
            cvt8(*(const uint4*)(fr + j * 1024 + 256 + h * 64 + sub * 8), k8);
            float acc = 0.f;
#pragma unroll
            for (int i = 0; i < 8; i++) acc = fmaf(q8[i], k8[i], acc);
            dot[j] = acc;
        }
    }
#pragma unroll
    for (int j = 0; j < 4; j++)
#pragma unroll
        for (int o = 4; o > 0; o >>= 1)
            dot[j] += __shfl_xor_sync(0xffffffffu, dot[j], o);

    // masked softmax for head h (== this lane's feature head)
    float alpha[4];
    {
        float m = -1e30f;
#pragma unroll
        for (int j = 0; j < 4; j++) if (j != node) m = fmaxf(m, dot[j] * 0.125f);
        float sum = 0.f;
#pragma unroll
        for (int j = 0; j < 4; j++) {
            alpha[j] = (j == node) ? 0.f : expf(dot[j] * 0.125f - m);
            sum += alpha[j];
        }
        float inv = 1.f / sum;
#pragma unroll
        for (int j = 0; j < 4; j++) alpha[j] *= inv;
    }

    // features f = lane*8 .. +7 (head h): o = sum_j alpha_j * v_j  (128-bit LDS)
    const int f0 = lane * 8;
    float o8[8] = {0.f, 0.f, 0.f, 0.f, 0.f, 0.f, 0.f, 0.f};
#pragma unroll
    for (int j = 0; j < 4; j++) {
        float v8[8];
        cvt8(*(const uint4*)(fr + j * 1024 + 512 + f0), v8);
#pragma unroll
        for (int i = 0; i < 8; i++) o8[i] = fmaf(alpha[j], v8[i], o8[i]);
    }
    float xr8[8];
    cvt8(*(const uint4*)(fr + node * 1024 + 768 + f0), xr8);

    // beta gate (128-bit global loads; L1-resident after first frames)
    float bw0[8], bw1[8], bw2[8];
    *(float4*)&bw0[0] = *(const float4*)(bw + f0);
    *(float4*)&bw0[4] = *(const float4*)(bw + f0 + 4);
    *(float4*)&bw1[0] = *(const float4*)(bw + 256 + f0);
    *(float4*)&bw1[4] = *(const float4*)(bw + 256 + f0 + 4);
    *(float4*)&bw2[0] = *(const float4*)(bw + 512 + f0);
    *(float4*)&bw2[4] = *(const float4*)(bw + 512 + f0 + 4);
    float bsum = 0.f;
#pragma unroll
    for (int i = 0; i < 8; i++)
        bsum += o8[i] * bw0[i] + xr8[i] * bw1[i] + (o8[i] - xr8[i]) * bw2[i];
    bsum = warp_sum(bsum);
    const float beta = 1.f / (1.f + expf(-bsum));

    float y8[8];
    float ssum = 0.f, ssq = 0.f;
#pragma unroll
    for (int i = 0; i < 8; i++) {
        y8[i] = beta * xr8[i] + (1.f - beta) * o8[i];
        ssum += y8[i];
        ssq  += y8[i] * y8[i];
    }
    ssum = warp_sum(ssum);
    ssq  = warp_sum(ssq);
    const float mu  = ssum * (1.f / 256.f);
    const float var = ssq * (1.f / 256.f) - mu * mu;
    const float inv = rsqrtf(var + 1e-5f);

    float g8[8], b8[8];
    *(float4*)&g8[0] = *(const float4*)(ln_g + f0);
    *(float4*)&g8[4] = *(const float4*)(ln_g + f0 + 4);
    *(float4*)&b8[0] = *(const float4*)(ln_b + f0);
    *(float4*)&b8[4] = *(const float4*)(ln_b + f0 + 4);
    float r8[8];
#pragma unroll
    for (int i = 0; i < 8; i++)
        r8[i] = fmaxf((y8[i] - mu) * inv * g8[i] + b8[i], 0.f);

    const size_t row = (size_t)blockIdx.x * 8 + fl * 4 + node;
    store8(out + row * 256 + f0, r8);
}

// ---------------------------------------------------------------------------
// Launch sequence
// ---------------------------------------------------------------------------
extern "C" void kernel_launch(void* const* d_in, const int* in_sizes, int n_in,
                              void* d_out, int out_size)
{
    (void)in_sizes; (void)n_in; (void)out_size;
    const float* x     = (const float*)d_in[0];
    const float* emb_w = (const float*)d_in[1];
    const float* emb_b = (const float*)d_in[2];
    const float* q1w = (const float*)d_in[3];  const float* q1b = (const float*)d_in[4];
    const float* k1w = (const float*)d_in[5];  const float* k1b = (const float*)d_in[6];
    const float* v1w = (const float*)d_in[7];  const float* v1b = (const float*)d_in[8];
    const float* s1w = (const float*)d_in[9];  const float* s1b = (const float*)d_in[10];
    const float* b1w = (const float*)d_in[11];
    const float* ln1_g = (const float*)d_in[12]; const float* ln1_b = (const float*)d_in[13];
    const float* q2w = (const float*)d_in[14]; const float* q2b = (const float*)d_in[15];
    const float* k2w = (const float*)d_in[16]; const float* k2b = (const float*)d_in[17];
    const float* v2w = (const float*)d_in[18]; const float* v2b = (const float*)d_in[19];
    const float* s2w = (const float*)d_in[20]; const float* s2b = (const float*)d_in[21];
    const float* b2w = (const float*)d_in[22];
    const float* ln2_g = (const float*)d_in[23]; const float* ln2_b = (const float*)d_in[24];
    float* out = (float*)d_out;

    __half *xh, *h, *qkvs, *wemb, *w1, *w2;
    float *bemb, *b1, *b2;
    cudaGetSymbolAddress((void**)&xh, g_x);
    cudaGetSymbolAddress((void**)&h, g_h);
    cudaGetSymbolAddress((void**)&qkvs, g_qkvs);
    cudaGetSymbolAddress((void**)&wemb, g_wemb);
    cudaGetSymbolAddress((void**)&w1, g_w1);
    cudaGetSymbolAddress((void**)&w2, g_w2);
    cudaGetSymbolAddress((void**)&bemb, g_bemb);
    cudaGetSymbolAddress((void**)&b1, g_b1);
    cudaGetSymbolAddress((void**)&b2, g_b2);

    static int smem_set = 0;
    if (!smem_set) {
        cudaFuncSetAttribute(gemm_f16<2>,
                             cudaFuncAttributeMaxDynamicSharedMemorySize, GEMM_SMEM);
        cudaFuncSetAttribute(gemm_f16<4>,
                             cudaFuncAttributeMaxDynamicSharedMemorySize, GEMM_SMEM);
        smem_set = 1;
    }

    // single prep launch: convert x + pack all weights
    prep_all<<<18560, 256>>>(x, xh, emb_w, emb_b,
                             q1w, k1w, v1w, s1w, q1b, k1b, v1b, s1b,
                             q2w, k2w, v2w, s2w, q2b, k2b, v2b, s2b);

    // embedding (K=128)
    gemm_f16<2><<<dim3(DIM_F / 128, NROWS / 128), 256, GEMM_SMEM>>>(
        xh, wemb, bemb, h, DIM_F, 1);

    // conv1 (K=256)
    gemm_f16<4><<<dim3(DIM_QKVS / 128, NROWS / 128), 256, GEMM_SMEM>>>(
        h, w1, b1, qkvs, DIM_QKVS, 0);
    attn_ln_kernel<__half><<<NFRAMES / 2, 256>>>(qkvs, b1w, ln1_g, ln1_b, h);

    // conv2 (K=256)
    gemm_f16<4><<<dim3(DIM_QKVS / 128, NROWS / 128), 256, GEMM_SMEM>>>(
        h, w2, b2, qkvs, DIM_QKVS, 0);
    attn_ln_kernel<float><<<NFRAMES / 2, 256>>>(qkvs, b2w, ln2_g, ln2_b, out);
}

// round 17
// speedup vs baseline: 1.0397x; 1.0397x over previous
#include <cuda_runtime.h>
#include <cuda_fp16.h>
#include <cstdint>
#include <math.h>

// ---------------------------------------------------------------------------
// B=16, T=2048, M=4, D=128, F=256, H=4, C=64
// Nf = 32768 frames, Nrows = 131072
// Toolchain targets sm_100 (no 'a') -> legacy mma.sync fp16 path.
// GEMM: BM=128 BN=128, 256 thr, 3-stage cp.async, 2 CTAs/SM (R13-proven).
// attn: R13 champion version, frozen.
// emb GEMM: reads x fp32 directly, converts during A-staging (kills convert_x).
// ---------------------------------------------------------------------------
#define NFRAMES   32768
#define NROWS     131072
#define DIM_D     128
#define DIM_F     256
#define DIM_QKVS  1024

__device__ __half g_h[NROWS * DIM_F];          // 64 MB: hidden activations
__device__ __half g_qkvs[NROWS * DIM_QKVS];    // 256 MB: fused q|k|v|s
__device__ __half g_wemb[DIM_F * DIM_D];       // emb weights [N][K]
__device__ __half g_w1[DIM_QKVS * DIM_F];      // conv1 packed weights [N][K]
__device__ __half g_w2[DIM_QKVS * DIM_F];      // conv2 packed weights [N][K]
__device__ float  g_bemb[DIM_F];
__device__ float  g_b1[DIM_QKVS];
__device__ float  g_b2[DIM_QKVS];

__device__ __forceinline__ uint32_t swz(uint32_t off) {   // 128B-row XOR swizzle
    return off ^ ((off >> 3) & 0x70);
}

#define CP_ASYNC16(dst, src) \
    asm volatile("cp.async.cg.shared.global [%0], [%1], 16;" :: "r"(dst), "l"(src))
#define CP_COMMIT() asm volatile("cp.async.commit_group;")
#define CP_WAIT1()  asm volatile("cp.async.wait_group 1;" ::: "memory")
#define CP_WAIT0()  asm volatile("cp.async.wait_group 0;" ::: "memory")

#define LDSM_X4(r, addr)                                                        \
    asm volatile("ldmatrix.sync.aligned.m8n8.x4.shared.b16 {%0,%1,%2,%3}, [%4];" \
                 : "=r"((r)[0]), "=r"((r)[1]), "=r"((r)[2]), "=r"((r)[3])        \
                 : "r"(addr))

#define MMA_F16(c, a, b0v, b1v)                                                 \
    asm volatile("mma.sync.aligned.m16n8k16.row.col.f32.f16.f16.f32 "           \
                 "{%0,%1,%2,%3},{%4,%5,%6,%7},{%8,%9},{%0,%1,%2,%3};"           \
                 : "+f"((c)[0]), "+f"((c)[1]), "+f"((c)[2]), "+f"((c)[3])        \
                 : "r"((a)[0]), "r"((a)[1]), "r"((a)[2]), "r"((a)[3]),           \
                   "r"(b0v), "r"(b1v))

// ---------------------------------------------------------------------------
// fp16 mma.sync GEMM (R13-proven config, unchanged).
// ---------------------------------------------------------------------------
#define ASZ (128 * 128)      // 16 KB (128 rows x 128 B)
#define BSZ (128 * 128)      // 16 KB
#define GEMM_SMEM (3 * (ASZ + BSZ))   // 98304 B -> 2 CTAs/SM

template <int NCHUNKS>
__global__ __launch_bounds__(256, 2)
void gemm_f16(const __half* __restrict__ A, const __half* __restrict__ Wt,
              const float* __restrict__ bias, __half* __restrict__ C,
              int NC, int relu)
{
    constexpr int K = NCHUNKS * 64;
    extern __shared__ __align__(128) char smem[];
    const uint32_t smem_u = (uint32_t)__cvta_generic_to_shared(smem);
    const uint32_t a_u = smem_u;
    const uint32_t b_u = smem_u + 3 * ASZ;

    const int tid  = threadIdx.x;
    const int lane = tid & 31;
    const int wid  = tid >> 5;
    const int wm   = wid >> 1;
    const int wn   = wid & 1;
    const int row0 = blockIdx.y * 128;
    const int col0 = blockIdx.x * 128;

    float acc[2][8][4];
#pragma unroll
    for (int mi = 0; mi < 2; mi++)
#pragma unroll
        for (int nf = 0; nf < 8; nf++)
#pragma unroll
            for (int c = 0; c < 4; c++) acc[mi][nf][c] = 0.f;

    const int ac = tid & 7;

    auto stage = [&](int s, int c) {
        const int k0 = c * 64;
        const uint32_t abase = a_u + s * ASZ;
        const uint32_t bbase = b_u + s * BSZ;
#pragma unroll
        for (int t = 0; t < 4; t++) {
            int rr = (tid + t * 256) >> 3;
            const __half* src = A + (size_t)(row0 + rr) * K + k0 + ac * 8;
            CP_ASYNC16(abase + swz(rr * 128 + ac * 16), src);
        }
#pragma unroll
        for (int t = 0; t < 4; t++) {
            int rr = (tid + t * 256) >> 3;
            const __half* src = Wt + (size_t)(col0 + rr) * K + k0 + ac * 8;
            CP_ASYNC16(bbase + swz(rr * 128 + ac * 16), src);
        }
    };

    stage(0, 0); CP_COMMIT();
    if (NCHUNKS > 1) stage(1, 1);
    CP_COMMIT();

    const int arow0 = wm * 32 + (lane & 15);
    const int ahc   = lane >> 4;
    const int brow0 = wn * 64 + (lane & 7) + ((lane >> 4) & 1) * 8;
    const int bhc   = (lane >> 3) & 1;

#pragma unroll
    for (int c = 0; c < NCHUNKS; c++) {
        const int s = c % 3;
        CP_WAIT1();
        __syncthreads();
        if (c + 2 < NCHUNKS) stage((c + 2) % 3, c + 2);
        CP_COMMIT();

        const uint32_t asb = a_u + s * ASZ;
        const uint32_t bsb = b_u + s * BSZ;
#pragma unroll
        for (int ks = 0; ks < 4; ks++) {
            unsigned a[2][4];
#pragma unroll
            for (int mi = 0; mi < 2; mi++) {
                int row = arow0 + mi * 16;
                int ch  = (ks * 2 + ahc) ^ (row & 7);
                LDSM_X4(a[mi], asb + (uint32_t)(row * 128 + ch * 16));
            }
            unsigned b[4][4];
#pragma unroll
            for (int p = 0; p < 4; p++) {
                int row = brow0 + p * 16;
                int ch  = (ks * 2 + bhc) ^ (row & 7);
                LDSM_X4(b[p], bsb + (uint32_t)(row * 128 + ch * 16));
            }
#pragma unroll
            for (int mi = 0; mi < 2; mi++)
#pragma unroll
                for (int nf = 0; nf < 8; nf++)
                    MMA_F16(acc[mi][nf], a[mi],
                            b[nf >> 1][(nf & 1) * 2], b[nf >> 1][(nf & 1) * 2 + 1]);
        }
        __syncthreads();
    }

    const int g = lane >> 2, t = lane & 3;
    float2 bb[8];
#pragma unroll
    for (int nf = 0; nf < 8; nf++)
        bb[nf] = *(const float2*)&bias[col0 + wn * 64 + nf * 8 + t * 2];

    CP_WAIT0();

#pragma unroll
    for (int mi = 0; mi < 2; mi++) {
        int row = row0 + wm * 32 + mi * 16 + g;
#pragma unroll
        for (int nf = 0; nf < 8; nf++) {
            int col = col0 + wn * 64 + nf * 8 + t * 2;
            float2 v0 = make_float2(acc[mi][nf][0] + bb[nf].x, acc[mi][nf][1] + bb[nf].y);
            float2 v1 = make_float2(acc[mi][nf][2] + bb[nf].x, acc[mi][nf][3] + bb[nf].y);
            if (relu) {
                v0.x = fmaxf(v0.x, 0.f); v0.y = fmaxf(v0.y, 0.f);
                v1.x = fmaxf(v1.x, 0.f); v1.y = fmaxf(v1.y, 0.f);
            }
            *(__half2*)&C[(size_t)row * NC + col]       = __floats2half2_rn(v0.x, v0.y);
            *(__half2*)&C[(size_t)(row + 8) * NC + col] = __floats2half2_rn(v1.x, v1.y);
        }
    }
}

// ---------------------------------------------------------------------------
// emb GEMM: A is fp32 x (K=128), converted to fp16 during staging.
// h = relu(x @ wemb^T + bemb). BM=128 BN=128, 2 chunks, both B chunks
// prefetched via cp.async; A staged LDG.128 -> cvt -> STS (same SW128 layout).
// smem: A 2x16KB + B 2x16KB = 64 KB -> 2 CTAs/SM.
// ---------------------------------------------------------------------------
#define EMB_SMEM (4 * 16384)

__global__ __launch_bounds__(256, 2)
void gemm_emb(const float* __restrict__ A, const __half* __restrict__ Wt,
              const float* __restrict__ bias, __half* __restrict__ C)
{
    extern __shared__ __align__(128) char smem[];
    const uint32_t smem_u = (uint32_t)__cvta_generic_to_shared(smem);
    const uint32_t a_u = smem_u;                 // 2 x 16 KB
    const uint32_t b_u = smem_u + 2 * ASZ;       // 2 x 16 KB

    const int tid  = threadIdx.x;
    const int lane = tid & 31;
    const int wid  = tid >> 5;
    const int wm   = wid >> 1;
    const int wn   = wid & 1;
    const int row0 = blockIdx.y * 128;
    const int col0 = blockIdx.x * 128;

    float acc[2][8][4];
#pragma unroll
    for (int mi = 0; mi < 2; mi++)
#pragma unroll
        for (int nf = 0; nf < 8; nf++)
#pragma unroll
            for (int c = 0; c < 4; c++) acc[mi][nf][c] = 0.f;

    const int ac = tid & 7;

    // prefetch BOTH B chunks (Wt rows = 128 halves; chunk s = halves s*64..+63)
#pragma unroll
    for (int s = 0; s < 2; s++)
#pragma unroll
        for (int t = 0; t < 4; t++) {
            int rr = (tid + t * 256) >> 3;
            const __half* src = Wt + (size_t)(col0 + rr) * DIM_D + s * 64 + ac * 8;
            CP_ASYNC16(b_u + s * BSZ + swz(rr * 128 + ac * 16), src);
        }
    CP_COMMIT();

    // A staging: chunk c = floats c*64..+63 per row; LDG.128 -> fp16 -> STS 8B
    auto stageA = [&](int s, int c) {
#pragma unroll
        for (int t = 0; t < 8; t++) {
            int idx = tid + t * 256;            // 0..2047
            int rr = idx >> 4;                  // row 0..127
            int c4 = idx & 15;                  // float4 within 64-float chunk
            float4 v = *(const float4*)(A + (size_t)(row0 + rr) * DIM_D + c * 64 + c4 * 4);
            char* dst = smem + s * ASZ + swz((uint32_t)(rr * 128 + (c4 >> 1) * 16))
                      + (c4 & 1) * 8;
            *(__half2*)(dst)     = __floats2half2_rn(v.x, v.y);
            *(__half2*)(dst + 4) = __floats2half2_rn(v.z, v.w);
        }
    };

    stageA(0, 0);
    CP_WAIT0();            // B resident
    __syncthreads();       // A0 visible
    stageA(1, 1);
    __syncthreads();       // A1 visible

    const int arow0 = wm * 32 + (lane & 15);
    const int ahc   = lane >> 4;
    const int brow0 = wn * 64 + (lane & 7) + ((lane >> 4) & 1) * 8;
    const int bhc   = (lane >> 3) & 1;

#pragma unroll
    for (int c = 0; c < 2; c++) {
        const uint32_t asb = a_u + c * ASZ;
        const uint32_t bsb = b_u + c * BSZ;
#pragma unroll
        for (int ks = 0; ks < 4; ks++) {
            unsigned a[2][4];
#pragma unroll
            for (int mi = 0; mi < 2; mi++) {
                int row = arow0 + mi * 16;
                int ch  = (ks * 2 + ahc) ^ (row & 7);
                LDSM_X4(a[mi], asb + (uint32_t)(row * 128 + ch * 16));
            }
            unsigned b[4][4];
#pragma unroll
            for (int p = 0; p < 4; p++) {
                int row = brow0 + p * 16;
                int ch  = (ks * 2 + bhc) ^ (row & 7);
                LDSM_X4(b[p], bsb + (uint32_t)(row * 128 + ch * 16));
            }
#pragma unroll
            for (int mi = 0; mi < 2; mi++)
#pragma unroll
                for (int nf = 0; nf < 8; nf++)
                    MMA_F16(acc[mi][nf], a[mi],
                            b[nf >> 1][(nf & 1) * 2], b[nf >> 1][(nf & 1) * 2 + 1]);
        }
    }

    // epilogue: bias + relu, NC = 256
    const int g = lane >> 2, t = lane & 3;
#pragma unroll
    for (int mi = 0; mi < 2; mi++) {
        int row = row0 + wm * 32 + mi * 16 + g;
#pragma unroll
        for (int nf = 0; nf < 8; nf++) {
            int col = col0 + wn * 64 + nf * 8 + t * 2;
            float2 bb = *(const float2*)&bias[col];
            float2 v0 = make_float2(fmaxf(acc[mi][nf][0] + bb.x, 0.f),
                                    fmaxf(acc[mi][nf][1] + bb.y, 0.f));
            float2 v1 = make_float2(fmaxf(acc[mi][nf][2] + bb.x, 0.f),
                                    fmaxf(acc[mi][nf][3] + bb.y, 0.f));
            *(__half2*)&C[(size_t)row * DIM_F + col]       = __floats2half2_rn(v0.x, v0.y);
            *(__half2*)&C[(size_t)(row + 8) * DIM_F + col] = __floats2half2_rn(v1.x, v1.y);
        }
    }
}

// ---------------------------------------------------------------------------
// Prep: transpose-pack all weights (x conversion now fused into gemm_emb).
// Blocks: [0,128) emb pack, [128,1152) conv1, [1152,2176) conv2.
// ---------------------------------------------------------------------------
__device__ __forceinline__ void pack4_body(int idx,
    const float* qw, const float* kw, const float* vw, const float* sw,
    const float* qb, const float* kb, const float* vb, const float* sb,
    __half* wTo, float* bo)
{
    int k = idx & 255;
    int n = idx >> 8;
    int sel = n >> 8, jj = n & 255;
    const float* w = (sel == 0) ? qw : (sel == 1) ? kw : (sel == 2) ? vw : sw;
    wTo[(size_t)n * 256 + k] = __float2half(w[(size_t)k * 256 + jj]);
    if (idx < DIM_QKVS) {
        int s2 = idx >> 8, j2 = idx & 255;
        const float* b = (s2 == 0) ? qb : (s2 == 1) ? kb : (s2 == 2) ? vb : sb;
        bo[idx] = b[j2];
    }
}

__global__ void prep_all(const float* emb_w, const float* emb_b,
                         const float* q1w, const float* k1w, const float* v1w, const float* s1w,
                         const float* q1b, const float* k1b, const float* v1b, const float* s1b,
                         const float* q2w, const float* k2w, const float* v2w, const float* s2w,
                         const float* q2b, const float* k2b, const float* v2b, const float* s2b)
{
    const int bid = blockIdx.x;
    const int tid = threadIdx.x;
    if (bid < 128) {                      // emb [128x256] -> [256x128]
        int idx = bid * 256 + tid;
        int k = idx % DIM_D;
        int n = idx / DIM_D;
        g_wemb[(size_t)n * DIM_D + k] = __float2half(emb_w[(size_t)k * 256 + n]);
        if (idx < 256) g_bemb[idx] = emb_b[idx];
    } else if (bid < 1152) {
        pack4_body((bid - 128) * 256 + tid, q1w, k1w, v1w, s1w,
                   q1b, k1b, v1b, s1b, g_w1, g_b1);
    } else {
        pack4_body((bid - 1152) * 256 + tid, q2w, k2w, v2w, s2w,
                   q2b, k2b, v2b, s2b, g_w2, g_b2);
    }
}

// ---------------------------------------------------------------------------
// Barrier-free fused attention + beta skip + LayerNorm + ReLU (R13, frozen).
// Block = 256 threads = 8 warps = 2 frames x 4 nodes; one warp per node.
// ---------------------------------------------------------------------------
__device__ __forceinline__ float warp_sum(float v) {
#pragma unroll
    for (int o = 16; o > 0; o >>= 1) v += __shfl_xor_sync(0xffffffffu, v, o);
    return v;
}

__device__ __forceinline__ void store2(__half* p, float a, float b) {
    *(__half2*)p = __floats2half2_rn(a, b);
}
__device__ __forceinline__ void store2(float* p, float a, float b) {
    *(float2*)p = make_float2(a, b);
}

template <typename OutT>
__global__ __launch_bounds__(256)
void attn_ln_kernel(const __half* __restrict__ qkvs, const float* __restrict__ bw,
                    const float* __restrict__ ln_g, const float* __restrict__ ln_b,
                    OutT* __restrict__ out)
{
    __shared__ __align__(16) __half s_all[8192];   // 2 frames x 4 nodes x 1024

    const int tid  = threadIdx.x;
    const int lane = tid & 31;
    const int wid  = tid >> 5;
    const int fl   = wid >> 2;
    const int node = wid & 3;

    {
        const uint4* src = (const uint4*)(qkvs + (size_t)blockIdx.x * 8192);
        uint4* dst = (uint4*)s_all;
#pragma unroll
        for (int r = 0; r < 4; r++) dst[tid + r * 256] = src[tid + r * 256];
    }
    __syncthreads();

    const __half* fr = s_all + fl * 4096;
    const int h = lane >> 3, sub = lane & 7;

    float dot[4];
    {
        const __half2* qp = (const __half2*)(fr + node * 1024 + h * 64 + sub * 8);
        float2 q[4];
#pragma unroll
        for (int c = 0; c < 4; c++) q[c] = __half22float2(qp[c]);
#pragma unroll
        for (int j = 0; j < 4; j++) {
            const __half2* kp = (const __half2*)(fr + j * 1024 + 256 + h * 64 + sub * 8);
            float acc = 0.f;
#pragma unroll
            for (int c = 0; c < 4; c++) {
                float2 kk = __half22float2(kp[c]);
                acc += q[c].x * kk.x + q[c].y * kk.y;
            }
            dot[j] = acc;
        }
    }
#pragma unroll
    for (int j = 0; j < 4; j++)
#pragma unroll
        for (int o = 4; o > 0; o >>= 1)
            dot[j] += __shfl_xor_sync(0xffffffffu, dot[j], o);

    float aown[4];
    {
        float m = -1e30f;
#pragma unroll
        for (int j = 0; j < 4; j++) if (j != node) m = fmaxf(m, dot[j] * 0.125f);
        float sum = 0.f;
#pragma unroll
        for (int j = 0; j < 4; j++) {
            aown[j] = (j == node) ? 0.f : expf(dot[j] * 0.125f - m);
            sum += aown[j];
        }
        float inv = 1.f / sum;
#pragma unroll
        for (int j = 0; j < 4; j++) aown[j] *= inv;
    }
    float alpha[4][4];
#pragma unroll
    for (int hh = 0; hh < 4; hh++)
#pragma unroll
        for (int j = 0; j < 4; j++)
            alpha[hh][j] = __shfl_sync(0xffffffffu, aown[j], hh * 8);

    float2 o2[4], xr2[4];
    float bsum = 0.f;
#pragma unroll
    for (int r = 0; r < 4; r++) {
        const int f = r * 64 + lane * 2;
        float2 o = make_float2(0.f, 0.f);
#pragma unroll
        for (int j = 0; j < 4; j++) {
            float2 v = __half22float2(*(const __half2*)(fr + j * 1024 + 512 + f));
            o.x = fmaf(alpha[r][j], v.x, o.x);
            o.y = fmaf(alpha[r][j], v.y, o.y);
        }
        float2 xr = __half22float2(*(const __half2*)(fr + node * 1024 + 768 + f));
        o2[r] = o; xr2[r] = xr;
        float2 b0 = *(const float2*)(bw + f);
        float2 b1 = *(const float2*)(bw + 256 + f);
        float2 b2 = *(const float2*)(bw + 512 + f);
        bsum += o.x * b0.x + o.y * b0.y + xr.x * b1.x + xr.y * b1.y
              + (o.x - xr.x) * b2.x + (o.y - xr.y) * b2.y;
    }
    bsum = warp_sum(bsum);
    const float beta = 1.f / (1.f + expf(-bsum));

    float2 y2[4];
    float ssum = 0.f, ssq = 0.f;
#pragma unroll
    for (int r = 0; r < 4; r++) {
        float yx = beta * xr2[r].x + (1.f - beta) * o2[r].x;
        float yy = beta * xr2[r].y + (1.f - beta) * o2[r].y;
        y2[r] = make_float2(yx, yy);
        ssum += yx + yy;
        ssq  += yx * yx + yy * yy;
    }
    ssum = warp_sum(ssum);
    ssq  = warp_sum(ssq);
    const float mu  = ssum * (1.f / 256.f);
    const float var = ssq * (1.f / 256.f) - mu * mu;
    const float inv = rsqrtf(var + 1e-5f);

    OutT* dst = out + (size_t)(blockIdx.x * 8 + fl * 4 + node) * 256;
#pragma unroll
    for (int r = 0; r < 4; r++) {
        const int f = r * 64 + lane * 2;
        float2 g = *(const float2*)(ln_g + f);
        float2 b = *(const float2*)(ln_b + f);
        float vx = fmaxf((y2[r].x - mu) * inv * g.x + b.x, 0.f);
        float vy = fmaxf((y2[r].y - mu) * inv * g.y + b.y, 0.f);
        store2(&dst[f], vx, vy);
    }
}

// ---------------------------------------------------------------------------
// Launch sequence
// ---------------------------------------------------------------------------
extern "C" void kernel_launch(void* const* d_in, const int* in_sizes, int n_in,
                              void* d_out, int out_size)
{
    (void)in_sizes; (void)n_in; (void)out_size;
    const float* x     = (const float*)d_in[0];
    const float* emb_w = (const float*)d_in[1];
    const float* emb_b = (const float*)d_in[2];
    const float* q1w = (const float*)d_in[3];  const float* q1b = (const float*)d_in[4];
    const float* k1w = (const float*)d_in[5];  const float* k1b = (const float*)d_in[6];
    const float* v1w = (const float*)d_in[7];  const float* v1b = (const float*)d_in[8];
    const float* s1w = (const float*)d_in[9];  const float* s1b = (const float*)d_in[10];
    const float* b1w = (const float*)d_in[11];
    const float* ln1_g = (const float*)d_in[12]; const float* ln1_b = (const float*)d_in[13];
    const float* q2w = (const float*)d_in[14]; const float* q2b = (const float*)d_in[15];
    const float* k2w = (const float*)d_in[16]; const float* k2b = (const float*)d_in[17];
    const float* v2w = (const float*)d_in[18]; const float* v2b = (const float*)d_in[19];
    const float* s2w = (const float*)d_in[20]; const float* s2b = (const float*)d_in[21];
    const float* b2w = (const float*)d_in[22];
    const float* ln2_g = (const float*)d_in[23]; const float* ln2_b = (const float*)d_in[24];
    float* out = (float*)d_out;

    __half *h, *qkvs, *wemb, *w1, *w2;
    float *bemb, *b1, *b2;
    cudaGetSymbolAddress((void**)&h, g_h);
    cudaGetSymbolAddress((void**)&qkvs, g_qkvs);
    cudaGetSymbolAddress((void**)&wemb, g_wemb);
    cudaGetSymbolAddress((void**)&w1, g_w1);
    cudaGetSymbolAddress((void**)&w2, g_w2);
    cudaGetSymbolAddress((void**)&bemb, g_bemb);
    cudaGetSymbolAddress((void**)&b1, g_b1);
    cudaGetSymbolAddress((void**)&b2, g_b2);

    static int smem_set = 0;
    if (!smem_set) {
        cudaFuncSetAttribute(gemm_f16<4>,
                             cudaFuncAttributeMaxDynamicSharedMemorySize, GEMM_SMEM);
        cudaFuncSetAttribute(gemm_emb,
                             cudaFuncAttributeMaxDynamicSharedMemorySize, EMB_SMEM);
        smem_set = 1;
    }

    // prep: pack weights only (x conversion fused into gemm_emb)
    prep_all<<<2176, 256>>>(emb_w, emb_b,
                            q1w, k1w, v1w, s1w, q1b, k1b, v1b, s1b,
                            q2w, k2w, v2w, s2w, q2b, k2b, v2b, s2b);

    // embedding: h = relu(x @ emb_w + emb_b), x fp32 read directly
    gemm_emb<<<dim3(DIM_F / 128, NROWS / 128), 256, EMB_SMEM>>>(x, wemb, bemb, h);

    // conv1 (K=256)
    gemm_f16<4><<<dim3(DIM_QKVS / 128, NROWS / 128), 256, GEMM_SMEM>>>(
        h, w1, b1, qkvs, DIM_QKVS, 0);
    attn_ln_kernel<__half><<<NFRAMES / 2, 256>>>(qkvs, b1w, ln1_g, ln1_b, h);

    // conv2 (K=256)
    gemm_f16<4><<<dim3(DIM_QKVS / 128, NROWS / 128), 256, GEMM_SMEM>>>(
        h, w2, b2, qkvs, DIM_QKVS, 0);
    attn_ln_kernel<float><<<NFRAMES / 2, 256>>>(qkvs, b2w, ln2_g, ln2_b, out);
}